// round 3
// baseline (speedup 1.0000x reference)
#include <cuda_runtime.h>
#include <math.h>

// Problem constants
#define B_  4
#define N_  2048
#define D_  1024
#define E_  16
#define C_  256
#define BNEC_ (4LL * 2048 * 16 * 256)   // 33,554,432 elements per output tensor
#define FLT_MIN_NORMAL 1.17549435082228750797e-38f  // 2^-126

// Scratch: logits laid out [b][e][n] so the per-(b,e) softmax/sort reads contiguously.
__device__ float g_logits[B_ * E_ * N_];

// ---------------------------------------------------------------------------
// Kernel 1: zero the whole output buffer (dispatch + combine + 2 scalar zeros).
// ---------------------------------------------------------------------------
__global__ void zero_kernel(float* __restrict__ out, long long n) {
    long long n4 = n >> 2;
    float4* o4 = reinterpret_cast<float4*>(out);
    long long i = (long long)blockIdx.x * blockDim.x + threadIdx.x;
    long long stride = (long long)gridDim.x * blockDim.x;
    float4 z = make_float4(0.f, 0.f, 0.f, 0.f);
    for (long long k = i; k < n4; k += stride) o4[k] = z;
    long long tail = n4 << 2;
    if (i < n - tail) out[tail + i] = 0.f;
}

// ---------------------------------------------------------------------------
// Kernel 2: gate logits [b][e][n] = (key[b,n,:] . query[e,:]) / exp(temp).
// 32KB static SMEM tile of query (16 experts x 512 dims), two phases over D.
// Each warp owns 4 tokens; float4 loads; each SMEM query float4 feeds 16 FMAs.
// ---------------------------------------------------------------------------
__global__ __launch_bounds__(256) void logits_kernel(
        const float* __restrict__ key,
        const float* __restrict__ query,
        const float* __restrict__ temp) {
    __shared__ float sq[E_ * 512];   // 32 KB

    const int lane = threadIdx.x & 31;
    const int warp = threadIdx.x >> 5;
    const int tok0 = (blockIdx.x * 8 + warp) * 4;

    float acc[4][E_];
    #pragma unroll
    for (int t = 0; t < 4; t++)
        #pragma unroll
        for (int e = 0; e < E_; e++) acc[t][e] = 0.f;

    for (int phase = 0; phase < 2; ++phase) {
        for (int i = threadIdx.x; i < E_ * 512; i += 256) {
            int e = i >> 9, j = i & 511;
            sq[i] = query[e * D_ + phase * 512 + j];
        }
        __syncthreads();

        const float4* sq4 = reinterpret_cast<const float4*>(sq);
        #pragma unroll
        for (int i = 0; i < 4; ++i) {
            int dv = lane + 32 * i;
            float4 kv[4];
            #pragma unroll
            for (int t = 0; t < 4; ++t)
                kv[t] = reinterpret_cast<const float4*>(
                            key + (long long)(tok0 + t) * D_ + phase * 512)[dv];
            #pragma unroll
            for (int e = 0; e < E_; ++e) {
                float4 q = sq4[e * 128 + dv];
                #pragma unroll
                for (int t = 0; t < 4; ++t) {
                    acc[t][e] += kv[t].x * q.x;
                    acc[t][e] += kv[t].y * q.y;
                    acc[t][e] += kv[t].z * q.z;
                    acc[t][e] += kv[t].w * q.w;
                }
            }
        }
        __syncthreads();
    }

    const float et = expf(temp[0]);
    #pragma unroll
    for (int t = 0; t < 4; ++t) {
        int tok = tok0 + t;
        int b = tok >> 11, n = tok & (N_ - 1);
        #pragma unroll
        for (int e = 0; e < E_; ++e) {
            float v = acc[t][e];
            #pragma unroll
            for (int off = 16; off > 0; off >>= 1)
                v += __shfl_xor_sync(0xffffffffu, v, off);
            if (lane == 0)
                g_logits[(b * E_ + e) * N_ + n] = v / et;
        }
    }
}

// ---------------------------------------------------------------------------
// Kernel 3: per (b,e) row — softmax over 2048 tokens with SUBNORMAL AFFINITIES
// FLUSHED TO ZERO (matches reference/XLA ftz semantics — this drives the tie
// structure that jax.lax.top_k resolves by lowest-index-first), full bitonic
// sort by (affinity desc, index asc), scatter top-256.
// ---------------------------------------------------------------------------
__global__ void topk_scatter_kernel(float* __restrict__ out, long long out_n) {
    __shared__ float sv[N_];
    __shared__ int   si[N_];
    __shared__ float red[32];

    const int be = blockIdx.x;            // 0..63
    const int b = be / E_, e = be - b * E_;
    const float* row = g_logits + (long long)be * N_;
    const int tid = threadIdx.x, nt = blockDim.x;
    const int nwar = nt >> 5;

    for (int i = tid; i < N_; i += nt) { sv[i] = row[i]; si[i] = i; }
    __syncthreads();

    // ---- row max ----
    float m = -INFINITY;
    for (int i = tid; i < N_; i += nt) m = fmaxf(m, sv[i]);
    #pragma unroll
    for (int off = 16; off > 0; off >>= 1)
        m = fmaxf(m, __shfl_xor_sync(0xffffffffu, m, off));
    if ((tid & 31) == 0) red[tid >> 5] = m;
    __syncthreads();
    if (tid < 32) {
        float v = (tid < nwar) ? red[tid] : -INFINITY;
        #pragma unroll
        for (int off = 16; off > 0; off >>= 1)
            v = fmaxf(v, __shfl_xor_sync(0xffffffffu, v, off));
        if (tid == 0) red[0] = v;
    }
    __syncthreads();
    m = red[0];
    __syncthreads();

    // ---- exp + sum ----
    float s = 0.f;
    for (int i = tid; i < N_; i += nt) {
        float ev = expf(sv[i] - m);
        sv[i] = ev;
        s += ev;
    }
    #pragma unroll
    for (int off = 16; off > 0; off >>= 1)
        s += __shfl_xor_sync(0xffffffffu, s, off);
    if ((tid & 31) == 0) red[tid >> 5] = s;
    __syncthreads();
    if (tid < 32) {
        float v = (tid < nwar) ? red[tid] : 0.f;
        #pragma unroll
        for (int off = 16; off > 0; off >>= 1)
            v += __shfl_xor_sync(0xffffffffu, v, off);
        if (tid == 0) red[0] = v;
    }
    __syncthreads();
    const float S = red[0];
    __syncthreads();

    // ---- normalize with flush-to-zero on subnormal results ----
    for (int i = tid; i < N_; i += nt) {
        float a = sv[i] / S;
        if (a < FLT_MIN_NORMAL) a = 0.f;   // XLA ftz: subnormal affinity == 0
        sv[i] = a;
    }
    __syncthreads();

    // ---- bitonic sort: comparator order = (value desc, index asc) ----
    for (int k = 2; k <= N_; k <<= 1) {
        for (int j = k >> 1; j > 0; j >>= 1) {
            for (int i = tid; i < N_; i += nt) {
                int l = i ^ j;
                if (l > i) {
                    float v1 = sv[i], v2 = sv[l];
                    int i1 = si[i], i2 = si[l];
                    bool before = (v1 > v2) || (v1 == v2 && i1 < i2);
                    bool asc = ((i & k) == 0);
                    if (asc ? !before : before) {
                        sv[i] = v2; sv[l] = v1;
                        si[i] = i2; si[l] = i1;
                    }
                }
            }
            __syncthreads();
        }
    }

    // ---- scatter top-256 ----
    const bool has_combine = (out_n >= 2 * BNEC_);
    for (int c = tid; c < C_; c += nt) {
        int n = si[c];
        long long off = (((long long)b * N_ + n) * E_ + e) * C_ + c;
        out[off] = 1.0f;                             // dispatch_st forward value
        if (has_combine) out[BNEC_ + off] = sv[c];   // combine
    }
}

// ---------------------------------------------------------------------------
extern "C" void kernel_launch(void* const* d_in, const int* in_sizes, int n_in,
                              void* d_out, int out_size) {
    const float* key = nullptr; const float* query = nullptr; const float* temp = nullptr;
    for (int i = 0; i < n_in; ++i) {
        if (in_sizes[i] == B_ * N_ * D_)      key   = (const float*)d_in[i];
        else if (in_sizes[i] == E_ * D_)      query = (const float*)d_in[i];
        else if (in_sizes[i] == 1)            temp  = (const float*)d_in[i];
    }
    if (!key)   key   = (const float*)d_in[0];
    if (!query) query = (const float*)d_in[1];
    if (!temp)  temp  = (const float*)d_in[2];
    float* out = (float*)d_out;

    // 1) zero the whole output (268 MB — the bandwidth floor of this problem)
    zero_kernel<<<4096, 256>>>(out, (long long)out_size);
    // 2) gate logits (divided by exp(temp)), layout [b][e][n]
    logits_kernel<<<256, 256>>>(key, query, temp);
    // 3) softmax (ftz) + sorted top-256 + scatter (stream-ordered after 1 & 2)
    topk_scatter_kernel<<<B_ * E_, 512>>>(out, (long long)out_size);
}

// round 4
// speedup vs baseline: 1.2644x; 1.2644x over previous
#include <cuda_runtime.h>
#include <math.h>
#include <stdint.h>

// Problem constants
#define B_  4
#define N_  2048
#define D_  1024
#define E_  16
#define C_  256
#define BNEC_ (4LL * 2048 * 16 * 256)   // 33,554,432 elements per output tensor
#define FLT_MIN_NORMAL 1.17549435082228750797e-38f  // 2^-126

// Scratch
__device__ float              g_logits[B_ * E_ * N_];        // [b][e][n]
__device__ unsigned long long g_topk[B_ * E_ * C_];          // packed (valbits<<32)|(2047-idx)

// ---------------------------------------------------------------------------
// Kernel 1: gate logits [b][e][n] = (key[b,n,:] . query[e,:]) / exp(temp).
// 32KB SMEM query tile (16 x 512), two phases over D. 4 tokens per warp.
// ---------------------------------------------------------------------------
__global__ __launch_bounds__(256) void logits_kernel(
        const float* __restrict__ key,
        const float* __restrict__ query,
        const float* __restrict__ temp) {
    __shared__ float sq[E_ * 512];   // 32 KB

    const int lane = threadIdx.x & 31;
    const int warp = threadIdx.x >> 5;
    const int tok0 = (blockIdx.x * 8 + warp) * 4;

    float acc[4][E_];
    #pragma unroll
    for (int t = 0; t < 4; t++)
        #pragma unroll
        for (int e = 0; e < E_; e++) acc[t][e] = 0.f;

    for (int phase = 0; phase < 2; ++phase) {
        for (int i = threadIdx.x; i < E_ * 512; i += 256) {
            int e = i >> 9, j = i & 511;
            sq[i] = query[e * D_ + phase * 512 + j];
        }
        __syncthreads();

        const float4* sq4 = reinterpret_cast<const float4*>(sq);
        #pragma unroll
        for (int i = 0; i < 4; ++i) {
            int dv = lane + 32 * i;
            float4 kv[4];
            #pragma unroll
            for (int t = 0; t < 4; ++t)
                kv[t] = reinterpret_cast<const float4*>(
                            key + (long long)(tok0 + t) * D_ + phase * 512)[dv];
            #pragma unroll
            for (int e = 0; e < E_; ++e) {
                float4 q = sq4[e * 128 + dv];
                #pragma unroll
                for (int t = 0; t < 4; ++t) {
                    acc[t][e] += kv[t].x * q.x;
                    acc[t][e] += kv[t].y * q.y;
                    acc[t][e] += kv[t].z * q.z;
                    acc[t][e] += kv[t].w * q.w;
                }
            }
        }
        __syncthreads();
    }

    const float et = expf(temp[0]);
    #pragma unroll
    for (int t = 0; t < 4; ++t) {
        int tok = tok0 + t;
        int b = tok >> 11, n = tok & (N_ - 1);
        #pragma unroll
        for (int e = 0; e < E_; ++e) {
            float v = acc[t][e];
            #pragma unroll
            for (int off = 16; off > 0; off >>= 1)
                v += __shfl_xor_sync(0xffffffffu, v, off);
            if (lane == 0)
                g_logits[(b * E_ + e) * N_ + n] = v / et;
        }
    }
}

// ---------------------------------------------------------------------------
// Kernel 2: per (b,e) row — softmax (subnormals flushed to 0, matching XLA
// ftz semantics that define the tie structure), then full bitonic sort of
// packed 64-bit keys: (affinity_bits << 32) | (2047 - idx).
// affinity >= 0 so float bits are order-monotonic; key order == (value desc,
// index asc) == jax.lax.top_k order, decode is bit-exact.
// 1024 threads: one comparator per thread per sub-stage.
// ---------------------------------------------------------------------------
__global__ __launch_bounds__(1024) void topk_kernel() {
    __shared__ float              sv[N_];
    __shared__ unsigned long long sk[N_];
    __shared__ float              red[32];

    const int be  = blockIdx.x;           // 0..63
    const float* row = g_logits + (long long)be * N_;
    const int t = threadIdx.x;

    float x0 = row[t], x1 = row[t + 1024];
    sv[t] = x0; sv[t + 1024] = x1;

    // ---- block max ----
    float m = fmaxf(x0, x1);
    #pragma unroll
    for (int off = 16; off > 0; off >>= 1)
        m = fmaxf(m, __shfl_xor_sync(0xffffffffu, m, off));
    if ((t & 31) == 0) red[t >> 5] = m;
    __syncthreads();
    if (t < 32) {
        float v = red[t];
        #pragma unroll
        for (int off = 16; off > 0; off >>= 1)
            v = fmaxf(v, __shfl_xor_sync(0xffffffffu, v, off));
        if (t == 0) red[0] = v;
    }
    __syncthreads();
    m = red[0];
    __syncthreads();

    // ---- exp + sum ----
    float e0 = expf(x0 - m), e1 = expf(x1 - m);
    float s = e0 + e1;
    #pragma unroll
    for (int off = 16; off > 0; off >>= 1)
        s += __shfl_xor_sync(0xffffffffu, s, off);
    if ((t & 31) == 0) red[t >> 5] = s;
    __syncthreads();
    if (t < 32) {
        float v = red[t];
        #pragma unroll
        for (int off = 16; off > 0; off >>= 1)
            v += __shfl_xor_sync(0xffffffffu, v, off);
        if (t == 0) red[0] = v;
    }
    __syncthreads();
    const float S = red[0];

    // ---- normalize (ftz) + pack keys ----
    float a0 = e0 / S; if (a0 < FLT_MIN_NORMAL) a0 = 0.f;
    float a1 = e1 / S; if (a1 < FLT_MIN_NORMAL) a1 = 0.f;
    sk[t]        = ((unsigned long long)__float_as_uint(a0) << 32)
                 | (unsigned long long)(2047 - t);
    sk[t + 1024] = ((unsigned long long)__float_as_uint(a1) << 32)
                 | (unsigned long long)(2047 - (t + 1024));
    __syncthreads();

    // ---- bitonic sort, descending by key ----
    for (int k = 2; k <= N_; k <<= 1) {
        for (int j = k >> 1; j > 0; j >>= 1) {
            int i = 2 * t - (t & (j - 1));
            int l = i + j;
            unsigned long long A = sk[i], Bv = sk[l];
            bool dir = ((i & k) == 0);              // descending region
            bool sw  = dir ? (A < Bv) : (A > Bv);
            if (sw) { sk[i] = Bv; sk[l] = A; }
            __syncthreads();
        }
    }

    // ---- emit top-256 packed keys ----
    if (t < C_) g_topk[be * C_ + t] = sk[t];
}

// ---------------------------------------------------------------------------
// Kernel 3: zero the whole output buffer. Streaming stores (evict-first).
// ---------------------------------------------------------------------------
__global__ void zero_kernel(float* __restrict__ out, long long n) {
    long long n4 = n >> 2;
    float4* o4 = reinterpret_cast<float4*>(out);
    long long i = (long long)blockIdx.x * blockDim.x + threadIdx.x;
    long long stride = (long long)gridDim.x * blockDim.x;
    float4 z = make_float4(0.f, 0.f, 0.f, 0.f);
    for (long long k = i; k < n4; k += stride) __stcs(&o4[k], z);
    long long tail = n4 << 2;
    if (i < n - tail) out[tail + i] = 0.f;
}

// ---------------------------------------------------------------------------
// Kernel 4: scatter top-256 into dispatch (1.0) and combine (affinity).
// ---------------------------------------------------------------------------
__global__ __launch_bounds__(256) void scatter_kernel(float* __restrict__ out,
                                                      long long out_n) {
    const int be = blockIdx.x;            // 0..63
    const int b = be / E_, e = be - b * E_;
    const int c = threadIdx.x;            // 0..255
    unsigned long long K = g_topk[be * C_ + c];
    int   n = 2047 - (int)(K & 0x7FFu);
    float v = __uint_as_float((unsigned int)(K >> 32));
    long long off = (((long long)b * N_ + n) * E_ + e) * C_ + c;
    out[off] = 1.0f;                                   // dispatch_st forward
    if (out_n >= 2 * BNEC_) out[BNEC_ + off] = v;      // combine
}

// ---------------------------------------------------------------------------
extern "C" void kernel_launch(void* const* d_in, const int* in_sizes, int n_in,
                              void* d_out, int out_size) {
    const float* key = nullptr; const float* query = nullptr; const float* temp = nullptr;
    for (int i = 0; i < n_in; ++i) {
        if (in_sizes[i] == B_ * N_ * D_)      key   = (const float*)d_in[i];
        else if (in_sizes[i] == E_ * D_)      query = (const float*)d_in[i];
        else if (in_sizes[i] == 1)            temp  = (const float*)d_in[i];
    }
    if (!key)   key   = (const float*)d_in[0];
    if (!query) query = (const float*)d_in[1];
    if (!temp)  temp  = (const float*)d_in[2];
    float* out = (float*)d_out;

    // Order chosen so the compute chain precedes the bandwidth-bound fill and
    // only the tiny scatter depends on the fill (also rotates ncu's profiled
    // slot onto topk_kernel for the next diagnosis round).
    logits_kernel<<<256, 256>>>(key, query, temp);
    topk_kernel<<<B_ * E_, 1024>>>();
    zero_kernel<<<4096, 256>>>(out, (long long)out_size);
    scatter_kernel<<<B_ * E_, 256>>>(out, (long long)out_size);
}

// round 5
// speedup vs baseline: 1.4105x; 1.1156x over previous
#include <cuda_runtime.h>
#include <math.h>
#include <stdint.h>

// Problem constants
#define B_  4
#define N_  2048
#define D_  1024
#define E_  16
#define C_  256
#define BNEC_ (4LL * 2048 * 16 * 256)   // 33,554,432 elements per output tensor
#define FLT_MIN_NORMAL 1.17549435082228750797e-38f  // 2^-126

#define NLOG_BLOCKS 256
#define NZERO_BLOCKS 4096

// Scratch: logits laid out [b][e][n]
__device__ float g_logits[B_ * E_ * N_];

// ---------------------------------------------------------------------------
// Kernel 1 (fused): blocks [0, 256) compute gate logits; blocks [256, 4352)
// zero-fill the output with streaming float4 stores. The two jobs are
// independent (logits reads key/query; fill writes out), so the FFMA-bound
// logits work hides under the store-bandwidth-bound fill.
// ---------------------------------------------------------------------------
__global__ __launch_bounds__(256) void fused_zero_logits_kernel(
        const float* __restrict__ key,
        const float* __restrict__ query,
        const float* __restrict__ temp,
        float* __restrict__ out, long long out_n) {
    if (blockIdx.x >= NLOG_BLOCKS) {
        // ---------------- zero-fill path ----------------
        long long n4 = out_n >> 2;
        float4* o4 = reinterpret_cast<float4*>(out);
        long long i = (long long)(blockIdx.x - NLOG_BLOCKS) * 256 + threadIdx.x;
        long long stride = (long long)NZERO_BLOCKS * 256;
        float4 z = make_float4(0.f, 0.f, 0.f, 0.f);
        for (long long k = i; k < n4; k += stride) __stcs(&o4[k], z);
        long long tail = n4 << 2;
        if (i < out_n - tail) out[tail + i] = 0.f;
        return;
    }

    // ---------------- logits path ----------------
    // [b][e][n] = (key[b,n,:] . query[e,:]) / exp(temp)
    __shared__ float sq[E_ * 512];   // 32 KB query tile (16 experts x 512 dims)

    const int lane = threadIdx.x & 31;
    const int warp = threadIdx.x >> 5;
    const int tok0 = (blockIdx.x * 8 + warp) * 4;

    float acc[4][E_];
    #pragma unroll
    for (int t = 0; t < 4; t++)
        #pragma unroll
        for (int e = 0; e < E_; e++) acc[t][e] = 0.f;

    for (int phase = 0; phase < 2; ++phase) {
        for (int i = threadIdx.x; i < E_ * 512; i += 256) {
            int e = i >> 9, j = i & 511;
            sq[i] = query[e * D_ + phase * 512 + j];
        }
        __syncthreads();

        const float4* sq4 = reinterpret_cast<const float4*>(sq);
        #pragma unroll
        for (int i = 0; i < 4; ++i) {
            int dv = lane + 32 * i;
            float4 kv[4];
            #pragma unroll
            for (int t = 0; t < 4; ++t)
                kv[t] = reinterpret_cast<const float4*>(
                            key + (long long)(tok0 + t) * D_ + phase * 512)[dv];
            #pragma unroll
            for (int e = 0; e < E_; ++e) {
                float4 q = sq4[e * 128 + dv];
                #pragma unroll
                for (int t = 0; t < 4; ++t) {
                    acc[t][e] += kv[t].x * q.x;
                    acc[t][e] += kv[t].y * q.y;
                    acc[t][e] += kv[t].z * q.z;
                    acc[t][e] += kv[t].w * q.w;
                }
            }
        }
        __syncthreads();
    }

    const float et = expf(temp[0]);
    #pragma unroll
    for (int t = 0; t < 4; ++t) {
        int tok = tok0 + t;
        int b = tok >> 11, n = tok & (N_ - 1);
        #pragma unroll
        for (int e = 0; e < E_; ++e) {
            float v = acc[t][e];
            #pragma unroll
            for (int off = 16; off > 0; off >>= 1)
                v += __shfl_xor_sync(0xffffffffu, v, off);
            if (lane == 0)
                g_logits[(b * E_ + e) * N_ + n] = v / et;
        }
    }
}

// ---------------------------------------------------------------------------
// Kernel 2 (fused): per (b,e) row — softmax (subnormal affinities flushed to
// zero, matching XLA ftz semantics that define the tie structure), bitonic
// sort of packed 64-bit keys (affinity_bits << 32) | (2047 - idx)
// == (value desc, index asc) == jax.lax.top_k order — then scatter the
// top-256 straight into dispatch (1.0) and combine (affinity).
// Stream-ordered after K1, so the output is already zeroed.
// ---------------------------------------------------------------------------
__global__ __launch_bounds__(1024) void topk_scatter_kernel(
        float* __restrict__ out, long long out_n) {
    __shared__ unsigned long long sk[N_];
    __shared__ float red[32];

    const int be  = blockIdx.x;           // 0..63
    const int b = be / E_, e = be - b * E_;
    const float* row = g_logits + (long long)be * N_;
    const int t = threadIdx.x;

    float x0 = row[t], x1 = row[t + 1024];

    // ---- block max ----
    float m = fmaxf(x0, x1);
    #pragma unroll
    for (int off = 16; off > 0; off >>= 1)
        m = fmaxf(m, __shfl_xor_sync(0xffffffffu, m, off));
    if ((t & 31) == 0) red[t >> 5] = m;
    __syncthreads();
    if (t < 32) {
        float v = red[t];
        #pragma unroll
        for (int off = 16; off > 0; off >>= 1)
            v = fmaxf(v, __shfl_xor_sync(0xffffffffu, v, off));
        if (t == 0) red[0] = v;
    }
    __syncthreads();
    m = red[0];
    __syncthreads();

    // ---- exp + sum ----
    float e0 = expf(x0 - m), e1 = expf(x1 - m);
    float s = e0 + e1;
    #pragma unroll
    for (int off = 16; off > 0; off >>= 1)
        s += __shfl_xor_sync(0xffffffffu, s, off);
    if ((t & 31) == 0) red[t >> 5] = s;
    __syncthreads();
    if (t < 32) {
        float v = red[t];
        #pragma unroll
        for (int off = 16; off > 0; off >>= 1)
            v += __shfl_xor_sync(0xffffffffu, v, off);
        if (t == 0) red[0] = v;
    }
    __syncthreads();
    const float S = red[0];

    // ---- normalize (ftz) + pack keys ----
    float a0 = e0 / S; if (a0 < FLT_MIN_NORMAL) a0 = 0.f;
    float a1 = e1 / S; if (a1 < FLT_MIN_NORMAL) a1 = 0.f;
    sk[t]        = ((unsigned long long)__float_as_uint(a0) << 32)
                 | (unsigned long long)(2047 - t);
    sk[t + 1024] = ((unsigned long long)__float_as_uint(a1) << 32)
                 | (unsigned long long)(2047 - (t + 1024));
    __syncthreads();

    // ---- bitonic sort, descending by key; one comparator per thread ----
    for (int k = 2; k <= N_; k <<= 1) {
        for (int j = k >> 1; j > 0; j >>= 1) {
            int i = 2 * t - (t & (j - 1));
            int l = i + j;
            unsigned long long A = sk[i], Bv = sk[l];
            bool dir = ((i & k) == 0);              // descending region
            bool sw  = dir ? (A < Bv) : (A > Bv);
            if (sw) { sk[i] = Bv; sk[l] = A; }
            __syncthreads();
        }
    }

    // ---- scatter top-256 directly ----
    if (t < C_) {
        unsigned long long K = sk[t];
        int   n = 2047 - (int)(K & 0x7FFu);
        float v = __uint_as_float((unsigned int)(K >> 32));
        long long off = (((long long)b * N_ + n) * E_ + e) * C_ + t;
        out[off] = 1.0f;                                   // dispatch_st forward
        if (out_n >= 2 * BNEC_) out[BNEC_ + off] = v;      // combine
    }
}

// ---------------------------------------------------------------------------
extern "C" void kernel_launch(void* const* d_in, const int* in_sizes, int n_in,
                              void* d_out, int out_size) {
    const float* key = nullptr; const float* query = nullptr; const float* temp = nullptr;
    for (int i = 0; i < n_in; ++i) {
        if (in_sizes[i] == B_ * N_ * D_)      key   = (const float*)d_in[i];
        else if (in_sizes[i] == E_ * D_)      query = (const float*)d_in[i];
        else if (in_sizes[i] == 1)            temp  = (const float*)d_in[i];
    }
    if (!key)   key   = (const float*)d_in[0];
    if (!query) query = (const float*)d_in[1];
    if (!temp)  temp  = (const float*)d_in[2];
    float* out = (float*)d_out;

    // K1: zero-fill (268 MB, store-bound) + logits (FFMA-bound) run together.
    fused_zero_logits_kernel<<<NLOG_BLOCKS + NZERO_BLOCKS, 256>>>(
        key, query, temp, out, (long long)out_size);
    // K2: softmax + sorted top-256 + direct scatter (out already zeroed).
    topk_scatter_kernel<<<B_ * E_, 1024>>>(out, (long long)out_size);
}

// round 6
// speedup vs baseline: 1.8035x; 1.2786x over previous
#include <cuda_runtime.h>
#include <math.h>
#include <stdint.h>

// Problem constants
#define B_  4
#define N_  2048
#define D_  1024
#define E_  16
#define C_  256
#define BNEC_ (4LL * 2048 * 16 * 256)   // 33,554,432 elements per output tensor
#define FLT_MIN_NORMAL 1.17549435082228750797e-38f  // 2^-126

#define NLOG_BLOCKS 512          // 2 halves x 256
#define NZERO_BLOCKS 4096
#define HALF_OFF (B_ * E_ * N_)

// Partial logits: [half][b][e][n] (raw dots, un-scaled; K2 applies /exp(temp))
__device__ float g_plog[2 * B_ * E_ * N_];

// ---------------------------------------------------------------------------
// Kernel 1 (fused): blocks [0,512) compute half-D partial gate logits
// (block>>8 selects dim half); blocks [512, 4608) zero-fill the output with
// streaming float4 stores. Logits path is software-pipelined (prefetch next
// 4 key float4s before each FMA block; first loads issued before the SMEM
// staging sync) to survive the write-congested memory system.
// ---------------------------------------------------------------------------
__global__ __launch_bounds__(256) void fused_zero_logits_kernel(
        const float* __restrict__ key,
        const float* __restrict__ query,
        float* __restrict__ out, long long out_n) {
    if (blockIdx.x >= NLOG_BLOCKS) {
        // ---------------- zero-fill path ----------------
        long long n4 = out_n >> 2;
        float4* o4 = reinterpret_cast<float4*>(out);
        long long i = (long long)(blockIdx.x - NLOG_BLOCKS) * 256 + threadIdx.x;
        long long stride = (long long)NZERO_BLOCKS * 256;
        float4 z = make_float4(0.f, 0.f, 0.f, 0.f);
        for (long long k = i; k < n4; k += stride) __stcs(&o4[k], z);
        long long tail = n4 << 2;
        if (i < out_n - tail) out[tail + i] = 0.f;
        return;
    }

    // ---------------- logits path ----------------
    __shared__ float sq[E_ * 512];   // 32 KB: 16 experts x 512 dims (this half)

    const int lane = threadIdx.x & 31;
    const int warp = threadIdx.x >> 5;
    const int half = blockIdx.x >> 8;                    // dim half 0/1
    const int tok0 = (((int)blockIdx.x & 255) * 8 + warp) * 4;

    // Prefetch i=0 key vectors BEFORE staging sync (8 LDG.128 deep pipeline).
    const float4* kp[4];
    #pragma unroll
    for (int t = 0; t < 4; ++t)
        kp[t] = reinterpret_cast<const float4*>(
                    key + (long long)(tok0 + t) * D_ + half * 512);
    float4 kv[4], kvn[4];
    #pragma unroll
    for (int t = 0; t < 4; ++t) kv[t] = kp[t][lane];

    // Stage this half of query.
    for (int i = threadIdx.x; i < E_ * 512; i += 256) {
        int e = i >> 9, j = i & 511;
        sq[i] = query[e * D_ + half * 512 + j];
    }
    __syncthreads();

    float acc[4][E_];
    #pragma unroll
    for (int t = 0; t < 4; t++)
        #pragma unroll
        for (int e = 0; e < E_; e++) acc[t][e] = 0.f;

    const float4* sq4 = reinterpret_cast<const float4*>(sq);
    #pragma unroll
    for (int i = 0; i < 4; ++i) {
        if (i < 3) {
            int dvn = lane + 32 * (i + 1);
            #pragma unroll
            for (int t = 0; t < 4; ++t) kvn[t] = kp[t][dvn];
        }
        int dv = lane + 32 * i;
        #pragma unroll
        for (int e = 0; e < E_; ++e) {
            float4 q = sq4[e * 128 + dv];
            #pragma unroll
            for (int t = 0; t < 4; ++t) {
                acc[t][e] += kv[t].x * q.x;
                acc[t][e] += kv[t].y * q.y;
                acc[t][e] += kv[t].z * q.z;
                acc[t][e] += kv[t].w * q.w;
            }
        }
        #pragma unroll
        for (int t = 0; t < 4; ++t) kv[t] = kvn[t];
    }

    #pragma unroll
    for (int t = 0; t < 4; ++t) {
        int tok = tok0 + t;
        int b = tok >> 11, n = tok & (N_ - 1);
        #pragma unroll
        for (int e = 0; e < E_; ++e) {
            float v = acc[t][e];
            #pragma unroll
            for (int off = 16; off > 0; off >>= 1)
                v += __shfl_xor_sync(0xffffffffu, v, off);
            if (lane == 0)
                g_plog[half * HALF_OFF + (b * E_ + e) * N_ + n] = v;
        }
    }
}

// ---------------------------------------------------------------------------
// Kernel 2: per (b,e) row — softmax (ftz on subnormal affinities, matching
// XLA semantics), then SELECT-then-SORT:
//   * nonzero affinities (count m, typically ~50) compact in index order into
//     a 256-slot key array (packed (valbits<<32)|(2047-idx)), bitonic-sorted
//     descending by 128 threads using named barrier 1 -> exact jax top-k
//     order (value desc, index asc);
//   * slots [m,256) are the zero-affinity tokens in ascending index order,
//     written directly from a ballot prefix-scan (dispatch=1.0, combine=0
//     already zeroed).
// Fallback to a full 2048 bitonic sort if m > 256 (not expected).
// ---------------------------------------------------------------------------
__global__ __launch_bounds__(1024) void topk_scatter_kernel(
        const float* __restrict__ temp,
        float* __restrict__ out, long long out_n) {
    __shared__ unsigned long long sk[N_];   // full array only used in fallback
    __shared__ float red[32];
    __shared__ int scnt[64], sbase[64];
    __shared__ int mTot;

    const int be  = blockIdx.x;           // 0..63
    const int b = be / E_, e = be - b * E_;
    const float* rowA = g_plog + (long long)be * N_;
    const float* rowB = rowA + HALF_OFF;
    const int t = threadIdx.x;
    const int lane = t & 31, w = t >> 5;
    const float et = expf(temp[0]);

    float x0 = (rowA[t] + rowB[t]) / et;
    float x1 = (rowA[t + 1024] + rowB[t + 1024]) / et;

    // ---- block max ----
    float m = fmaxf(x0, x1);
    #pragma unroll
    for (int off = 16; off > 0; off >>= 1)
        m = fmaxf(m, __shfl_xor_sync(0xffffffffu, m, off));
    if (lane == 0) red[w] = m;
    __syncthreads();
    if (t < 32) {
        float v = red[t];
        #pragma unroll
        for (int off = 16; off > 0; off >>= 1)
            v = fmaxf(v, __shfl_xor_sync(0xffffffffu, v, off));
        if (t == 0) red[0] = v;
    }
    __syncthreads();
    m = red[0];
    __syncthreads();

    // ---- exp + sum ----
    float e0 = expf(x0 - m), e1 = expf(x1 - m);
    float s = e0 + e1;
    #pragma unroll
    for (int off = 16; off > 0; off >>= 1)
        s += __shfl_xor_sync(0xffffffffu, s, off);
    if (lane == 0) red[w] = s;
    __syncthreads();
    if (t < 32) {
        float v = red[t];
        #pragma unroll
        for (int off = 16; off > 0; off >>= 1)
            v += __shfl_xor_sync(0xffffffffu, v, off);
        if (t == 0) red[0] = v;
    }
    __syncthreads();
    const float S = red[0];

    // ---- normalize (ftz) ----
    float a0 = e0 / S; if (a0 < FLT_MIN_NORMAL) a0 = 0.f;
    float a1 = e1 / S; if (a1 < FLT_MIN_NORMAL) a1 = 0.f;
    const bool z0 = (a0 == 0.f), z1 = (a1 == 0.f);

    unsigned bal0 = __ballot_sync(0xffffffffu, z0);
    unsigned bal1 = __ballot_sync(0xffffffffu, z1);
    if (lane == 0) { scnt[w] = __popc(bal0); scnt[32 + w] = __popc(bal1); }
    if (t < C_) sk[t] = 0ull;          // pad slots for the 256-sort
    __syncthreads();

    // ---- one-warp exclusive scan over the 64 ordered chunks ----
    if (t < 32) {
        int c0 = scnt[t], c1 = scnt[t + 32];
        int s0 = c0;
        #pragma unroll
        for (int off = 1; off < 32; off <<= 1) {
            int v = __shfl_up_sync(0xffffffffu, s0, off);
            if (t >= off) s0 += v;
        }
        int tot0 = __shfl_sync(0xffffffffu, s0, 31);
        int s1 = c1;
        #pragma unroll
        for (int off = 1; off < 32; off <<= 1) {
            int v = __shfl_up_sync(0xffffffffu, s1, off);
            if (t >= off) s1 += v;
        }
        sbase[t] = s0 - c0;
        sbase[t + 32] = tot0 + s1 - c1;
        if (t == 31) mTot = 2 * 1024 - (tot0 + s1);   // # nonzero affinities
    }
    __syncthreads();
    const int mNZ = mTot;
    const unsigned lmask = (1u << lane) - 1u;
    const int zr0 = sbase[w]      + __popc(bal0 & lmask);   // zeros before idx t
    const int zr1 = sbase[32 + w] + __popc(bal1 & lmask);   // zeros before idx t+1024

    const bool hasC = (out_n >= 2 * BNEC_);

    if (mNZ <= C_) {
        // ---- compact nonzeros (index order == value-agnostic; sort fixes) ----
        if (!z0) {
            int r = t - zr0;                 // nonzero rank in index order
            sk[r] = ((unsigned long long)__float_as_uint(a0) << 32)
                  | (unsigned long long)(2047 - t);
        }
        if (!z1) {
            int r = (t + 1024) - zr1;
            sk[r] = ((unsigned long long)__float_as_uint(a1) << 32)
                  | (unsigned long long)(2047 - (t + 1024));
        }
        // ---- zero-affinity fill: slot c = m + zero_rank (index ascending) ----
        if (z0 && zr0 < C_ - mNZ) {
            long long off = (((long long)b * N_ + t) * E_ + e) * C_ + (mNZ + zr0);
            out[off] = 1.0f;                 // combine = 0, already zeroed
        }
        if (z1 && zr1 < C_ - mNZ) {
            long long off = (((long long)b * N_ + (t + 1024)) * E_ + e) * C_ + (mNZ + zr1);
            out[off] = 1.0f;
        }
        __syncthreads();

        // ---- bitonic sort of 256 keys, descending; warps 0-3 only ----
        if (t < 128) {
            for (int k = 2; k <= 256; k <<= 1) {
                for (int j = k >> 1; j > 0; j >>= 1) {
                    int i = 2 * t - (t & (j - 1));
                    int l = i + j;
                    unsigned long long A = sk[i], Bv = sk[l];
                    bool dir = ((i & k) == 0);
                    bool sw  = dir ? (A < Bv) : (A > Bv);
                    if (sw) { sk[i] = Bv; sk[l] = A; }
                    asm volatile("bar.sync 1, 128;" ::: "memory");
                }
            }
        }
        __syncthreads();

        // ---- scatter sorted nonzeros into slots [0, m) ----
        if (t < mNZ) {
            unsigned long long K = sk[t];
            int   n = 2047 - (int)(K & 0x7FFu);
            float v = __uint_as_float((unsigned int)(K >> 32));
            long long off = (((long long)b * N_ + n) * E_ + e) * C_ + t;
            out[off] = 1.0f;
            if (hasC) out[BNEC_ + off] = v;
        }
    } else {
        // ---- fallback (m > 256): full 2048-key bitonic sort ----
        sk[t]        = ((unsigned long long)__float_as_uint(a0) << 32)
                     | (unsigned long long)(2047 - t);
        sk[t + 1024] = ((unsigned long long)__float_as_uint(a1) << 32)
                     | (unsigned long long)(2047 - (t + 1024));
        __syncthreads();
        for (int k = 2; k <= N_; k <<= 1) {
            for (int j = k >> 1; j > 0; j >>= 1) {
                int i = 2 * t - (t & (j - 1));
                int l = i + j;
                unsigned long long A = sk[i], Bv = sk[l];
                bool dir = ((i & k) == 0);
                bool sw  = dir ? (A < Bv) : (A > Bv);
                if (sw) { sk[i] = Bv; sk[l] = A; }
                __syncthreads();
            }
        }
        if (t < C_) {
            unsigned long long K = sk[t];
            int   n = 2047 - (int)(K & 0x7FFu);
            float v = __uint_as_float((unsigned int)(K >> 32));
            long long off = (((long long)b * N_ + n) * E_ + e) * C_ + t;
            out[off] = 1.0f;
            if (hasC) out[BNEC_ + off] = v;
        }
    }
}

// ---------------------------------------------------------------------------
extern "C" void kernel_launch(void* const* d_in, const int* in_sizes, int n_in,
                              void* d_out, int out_size) {
    const float* key = nullptr; const float* query = nullptr; const float* temp = nullptr;
    for (int i = 0; i < n_in; ++i) {
        if (in_sizes[i] == B_ * N_ * D_)      key   = (const float*)d_in[i];
        else if (in_sizes[i] == E_ * D_)      query = (const float*)d_in[i];
        else if (in_sizes[i] == 1)            temp  = (const float*)d_in[i];
    }
    if (!key)   key   = (const float*)d_in[0];
    if (!query) query = (const float*)d_in[1];
    if (!temp)  temp  = (const float*)d_in[2];
    float* out = (float*)d_out;

    // K1: zero-fill (268 MB, store-bound) + pipelined half-D logits together.
    fused_zero_logits_kernel<<<NLOG_BLOCKS + NZERO_BLOCKS, 256>>>(
        key, query, out, (long long)out_size);
    // K2: softmax + select-then-sort top-256 + direct scatter.
    topk_scatter_kernel<<<B_ * E_, 1024>>>(temp, out, (long long)out_size);
}